// round 12
// baseline (speedup 1.0000x reference)
#include <cuda_runtime.h>

#define BB 8
#define LL 128
#define HH 768
#define HV (HH / 4)       // 192 float4 columns
#define NLAB 3
#define NSPLIT 4          // row-splits per batch in reduce_part_k

// scratch (allocation-free rule: __device__ globals)
__device__ __align__(16) float  g_o2[BB * LL * 2 * HH];    // partial o, 2 halves per (b,q)
__device__ __align__(16) float  g_cp_p[BB * LL * LL];      // compacted p
__device__ __align__(16) int    g_cp_i[BB * LL * LL];      // compacted Wv indices
__device__            int    g_nact[BB * LL];
__device__ __align__(16) float4 g_ps4[BB * NSPLIT * HV];   // partial sums
__device__ __align__(16) float4 g_pc4[BB * NSPLIT * HV];   // partial nonzero counts

// ---------------------------------------------------------------------------
// Kernel 1: scan + hidden + u (key dots) + softmax + compaction
// ---------------------------------------------------------------------------
__global__ __launch_bounds__(256) void key_k(
    const float* __restrict__ seq,    // [B,L,H]
    const float* __restrict__ Wk,     // [VOCAB,H]
    const int*   __restrict__ valid,  // [B,L]
    const int*   __restrict__ kvidx,  // [B,L]
    const int*   __restrict__ feat,   // [B,L,L]
    const int*   __restrict__ posm,   // [B,L,L]
    const int*   __restrict__ asp)    // [B,L]
{
    const int bq   = blockIdx.x;
    const int b    = bq / LL;
    const int q    = bq % LL;
    const int tid  = threadIdx.x;
    const int lane = tid & 31;
    const int wid  = tid >> 5;

    __shared__ __align__(16) float hid[HH];
    __shared__ float uk[LL];
    __shared__ int   fidx[LL];
    __shared__ int   wsum[4];
    __shared__ int   s_src;
    __shared__ int   s_nact;
    __shared__ float warp_red[8];
    __shared__ float s_dsum;

    if (tid == 0) { s_src = -1; s_nact = 0; }

    // ---- stable-partition scan: source row = q-th valid position ----
    int v = 0;
    unsigned mask = 0;
    if (tid < LL) v = valid[b * LL + tid];
    if (wid < 4) {
        mask = __ballot_sync(0xFFFFFFFFu, v != 0);
        if (lane == 0) wsum[wid] = __popc(mask);
    }
    if (tid < LL) fidx[tid] = feat[(size_t)bq * LL + tid];
    __syncthreads();
    if (wid < 4 && v) {
        int pref = __popc(mask & ((1u << lane) - 1u));
        if (wid > 0) pref += wsum[0];
        if (wid > 1) pref += wsum[1];
        if (wid > 2) pref += wsum[2];
        if (pref == q) s_src = tid;
    }
    __syncthreads();

    const int   aspv = asp[b * LL + q];
    const int   src  = s_src;
    const bool  hz   = (src < 0) || (aspv == 0);   // hidden row is all-zero
    const float aspf = (float)aspv;

    if (!hz) {
        // ---- stage hidden[b,q,:] ----
        for (int h = tid; h < HH; h += 256)
            hid[h] = aspf * seq[(size_t)(b * LL + src) * HH + h];
        __syncthreads();

        // ---- u[k] = dot(hid, Wk[kvidx[b,k]]) / sqrt(H); 2-key pipelined ----
        const float invscale = 1.0f / 27.712812921102035f;  // 1/sqrt(768)
        const float4* hv = (const float4*)hid;
        #pragma unroll 1
        for (int j = 0; j < 16; j += 2) {
            const int k0 = wid * 16 + j;
            const int idx0 = kvidx[b * LL + k0];
            const int idx1 = kvidx[b * LL + k0 + 1];
            // row 0 is valid memory; padding handled by final select
            const float4* r0 = (const float4*)(Wk + (size_t)idx0 * HH);
            const float4* r1 = (const float4*)(Wk + (size_t)idx1 * HH);
            float s0 = 0.f, s1 = 0.f;
            #pragma unroll 6
            for (int i = lane; i < HV; i += 32) {
                float4 c = hv[i];
                float4 a0 = __ldg(r0 + i);
                float4 a1 = __ldg(r1 + i);
                s0 += a0.x * c.x + a0.y * c.y + a0.z * c.z + a0.w * c.w;
                s1 += a1.x * c.x + a1.y * c.y + a1.z * c.z + a1.w * c.w;
            }
            #pragma unroll
            for (int off = 16; off; off >>= 1) {
                s0 += __shfl_xor_sync(0xFFFFFFFFu, s0, off);
                s1 += __shfl_xor_sync(0xFFFFFFFFu, s1, off);
            }
            if (lane == 0) {
                uk[k0]     = (idx0 != 0) ? s0 * invscale : 0.f;
                uk[k0 + 1] = (idx1 != 0) ? s1 * invscale : 0.f;
            }
        }
        __syncthreads();
    }

    // ---- delta = exp(u)*pos; block sum ----
    float dloc = 0.f;
    if (tid < LL) {
        int pm = posm[(size_t)bq * LL + tid];
        if (pm != 0) dloc = hz ? 1.f : expf(uk[tid]);   // exp(0)=1 when hz
    }
    float r = dloc;
    #pragma unroll
    for (int off = 16; off; off >>= 1) r += __shfl_xor_sync(0xFFFFFFFFu, r, off);
    if (lane == 0) warp_red[wid] = r;
    __syncthreads();
    if (tid == 0) {
        float t = 0.f;
        #pragma unroll
        for (int w = 0; w < 8; ++w) t += warp_red[w];
        s_dsum = t;
    }
    __syncthreads();
    const float inv = 1.f / (s_dsum + 1e-10f);

    // ---- compact active (p, idx) straight to global ----
    if (tid < LL && dloc != 0.f) {
        int idx = fidx[tid];
        if (idx != 0) {
            int slot = atomicAdd(&s_nact, 1);
            g_cp_p[(size_t)bq * LL + slot] = dloc * inv;
            g_cp_i[(size_t)bq * LL + slot] = idx;
        }
    }
    __syncthreads();
    if (tid == 0) g_nact[bq] = s_nact;
}

// ---------------------------------------------------------------------------
// Kernel 2: value gather. 2 blocks per (b,q): interleaved k-halves.
// ---------------------------------------------------------------------------
__global__ __launch_bounds__(192) void val_k(const float* __restrict__ Wv)
{
    const int bq   = blockIdx.x >> 1;
    const int half = blockIdx.x & 1;
    const int tid  = threadIdx.x;      // 0..191: float4 column

    __shared__ float sp_p[LL];
    __shared__ int   sp_i[LL];
    __shared__ int   s_n;

    if (tid == 0) s_n = g_nact[bq];
    __syncthreads();
    const int nact = s_n;
    for (int i = tid; i < nact; i += 192) {
        sp_p[i] = g_cp_p[(size_t)bq * LL + i];
        sp_i[i] = g_cp_i[(size_t)bq * LL + i];
    }
    __syncthreads();

    float4 acc = make_float4(0.f, 0.f, 0.f, 0.f);
    const float4* WvV = (const float4*)Wv;
    #pragma unroll 16
    for (int m = half; m < nact; m += 2) {
        float  pk = sp_p[m];
        float4 vv = __ldg(WvV + (size_t)sp_i[m] * HV + tid);
        acc.x += pk * vv.x; acc.y += pk * vv.y;
        acc.z += pk * vv.z; acc.w += pk * vv.w;
    }
    ((float4*)(g_o2 + ((size_t)bq * 2 + half) * HH))[tid] = acc;
}

// ---------------------------------------------------------------------------
// Kernel 3: grid = BB*NSPLIT, block = 192: partial (sum, count) over 32 rows.
// Sums the 2 halves of each row BEFORE the nonzero test (o = o0 + o1).
// ---------------------------------------------------------------------------
__global__ __launch_bounds__(192) void reduce_part_k() {
    const int blk = blockIdx.x;
    const int b   = blk / NSPLIT;
    const int sp  = blk % NSPLIT;
    const int t   = threadIdx.x;       // 0..191: float4 column

    const float4* ob = (const float4*)g_o2 + ((size_t)(b * LL + sp * 32) * 2) * HV + t;

    float4 s = make_float4(0.f, 0.f, 0.f, 0.f);
    float4 c = make_float4(0.f, 0.f, 0.f, 0.f);
    #pragma unroll 1
    for (int r0 = 0; r0 < 32; r0 += 8) {
        float4 v0[8], v1[8];
        #pragma unroll
        for (int j = 0; j < 8; ++j) {
            v0[j] = ob[(size_t)((r0 + j) * 2 + 0) * HV];   // 16 independent LDG.128
            v1[j] = ob[(size_t)((r0 + j) * 2 + 1) * HV];
        }
        #pragma unroll
        for (int j = 0; j < 8; ++j) {
            float4 vv;
            vv.x = v0[j].x + v1[j].x; vv.y = v0[j].y + v1[j].y;
            vv.z = v0[j].z + v1[j].z; vv.w = v0[j].w + v1[j].w;
            s.x += vv.x; s.y += vv.y; s.z += vv.z; s.w += vv.w;
            c.x += (vv.x != 0.f) ? 1.f : 0.f;
            c.y += (vv.y != 0.f) ? 1.f : 0.f;
            c.z += (vv.z != 0.f) ? 1.f : 0.f;
            c.w += (vv.w != 0.f) ? 1.f : 0.f;
        }
    }
    g_ps4[blk * HV + t] = s;
    g_pc4[blk * HV + t] = c;
}

// ---------------------------------------------------------------------------
// Kernel 4: grid = BB, block = 192: combine partials, emit logits.
// ---------------------------------------------------------------------------
__global__ __launch_bounds__(192) void head_k(
    const float* __restrict__ pooled,  // [B,H]
    const float* __restrict__ Wd,      // [3,2H]
    const float* __restrict__ bd,      // [3]
    float*       __restrict__ out)     // [B,3]
{
    const int b    = blockIdx.x;
    const int t    = threadIdx.x;      // 0..191
    const int lane = t & 31;
    const int wid  = t >> 5;           // 0..5

    __shared__ float wred[6][NLAB];

    float4 s = make_float4(0.f, 0.f, 0.f, 0.f);
    float4 c = make_float4(0.f, 0.f, 0.f, 0.f);
    #pragma unroll
    for (int sp = 0; sp < NSPLIT; ++sp) {
        float4 ps = g_ps4[(b * NSPLIT + sp) * HV + t];
        float4 pc = g_pc4[(b * NSPLIT + sp) * HV + t];
        s.x += ps.x; s.y += ps.y; s.z += ps.z; s.w += ps.w;
        c.x += pc.x; c.y += pc.y; c.z += pc.z; c.w += pc.w;
    }
    float4 avg = make_float4(s.x / c.x, s.y / c.y, s.z / c.z, s.w / c.w);
    float4 pv  = ((const float4*)pooled)[b * HV + t];

    #pragma unroll
    for (int n = 0; n < NLAB; ++n) {
        float4 w0 = ((const float4*)(Wd + n * 2 * HH))[t];
        float4 w1 = ((const float4*)(Wd + n * 2 * HH + HH))[t];
        float x = pv.x * w0.x + pv.y * w0.y + pv.z * w0.z + pv.w * w0.w
                + avg.x * w1.x + avg.y * w1.y + avg.z * w1.z + avg.w * w1.w;
        #pragma unroll
        for (int off = 16; off; off >>= 1)
            x += __shfl_xor_sync(0xFFFFFFFFu, x, off);
        if (lane == 0) wred[wid][n] = x;
    }
    __syncthreads();
    if (t < NLAB) {
        float tot = bd[t];
        #pragma unroll
        for (int w = 0; w < 6; ++w) tot += wred[w][t];
        out[b * NLAB + t] = tot;
    }
}

extern "C" void kernel_launch(void* const* d_in, const int* in_sizes, int n_in,
                              void* d_out, int out_size) {
    const float* seq    = (const float*)d_in[0];
    const float* pooled = (const float*)d_in[1];
    const float* Wk     = (const float*)d_in[2];
    const float* Wv     = (const float*)d_in[3];
    const float* Wd     = (const float*)d_in[4];
    const float* bd     = (const float*)d_in[5];
    const int*   valid  = (const int*)d_in[6];
    const int*   kvidx  = (const int*)d_in[7];
    const int*   feat   = (const int*)d_in[8];
    const int*   posm   = (const int*)d_in[9];
    const int*   asp    = (const int*)d_in[10];

    key_k<<<BB * LL, 256>>>(seq, Wk, valid, kvidx, feat, posm, asp);
    val_k<<<BB * LL * 2, 192>>>(Wv);
    reduce_part_k<<<BB * NSPLIT, 192>>>();
    head_k<<<BB, 192>>>(pooled, Wd, bd, (float*)d_out);
}

// round 13
// speedup vs baseline: 1.2115x; 1.2115x over previous
#include <cuda_runtime.h>

#define BB 8
#define LL 128
#define HH 768
#define HV (HH / 4)       // 192 float4 columns
#define NLAB 3

// o scratch [B, L, H]  (allocation-free rule: __device__ global)
__device__ __align__(16) float g_o[BB * LL * HH];

__global__ __launch_bounds__(256, 3) void attn_k(
    const float* __restrict__ seq,    // [B,L,H]
    const float* __restrict__ Wk,     // [VOCAB,H]
    const float* __restrict__ Wv,     // [FEAT_VOCAB,H]
    const int*   __restrict__ valid,  // [B,L]
    const int*   __restrict__ kvidx,  // [B,L]
    const int*   __restrict__ feat,   // [B,L,L]
    const int*   __restrict__ posm,   // [B,L,L]
    const int*   __restrict__ asp)    // [B,L]
{
    const int b    = blockIdx.x / LL;
    const int q    = blockIdx.x % LL;
    const int tid  = threadIdx.x;
    const int lane = tid & 31;
    const int wid  = tid >> 5;

    __shared__ __align__(16) float hid[HH];
    __shared__ float uk[LL];
    __shared__ float cp_p[LL];
    __shared__ int   cp_i[LL];
    __shared__ int   fidx[LL];
    __shared__ int   wsum[4];
    __shared__ int   s_src;
    __shared__ int   s_nact;
    __shared__ float warp_red[8];
    __shared__ float s_dsum;

    if (tid == 0) { s_src = -1; s_nact = 0; }

    // ---- stable-partition scan: source row = q-th valid position ----
    int v = 0;
    unsigned mask = 0;
    if (tid < LL) v = valid[b * LL + tid];
    if (wid < 4) {
        mask = __ballot_sync(0xFFFFFFFFu, v != 0);
        if (lane == 0) wsum[wid] = __popc(mask);
    }
    if (tid < LL) fidx[tid] = feat[(b * LL + q) * LL + tid];
    __syncthreads();
    if (wid < 4 && v) {
        int pref = __popc(mask & ((1u << lane) - 1u));
        if (wid > 0) pref += wsum[0];
        if (wid > 1) pref += wsum[1];
        if (wid > 2) pref += wsum[2];
        if (pref == q) s_src = tid;
    }
    __syncthreads();

    const int   aspv = asp[b * LL + q];
    const int   src  = s_src;
    const bool  hz   = (src < 0) || (aspv == 0);   // hidden row is all-zero
    const float aspf = (float)aspv;

    // ---- stage hidden[b,q,:] ----
    for (int h = tid; h < HH; h += 256)
        hid[h] = hz ? 0.f : aspf * seq[(size_t)(b * LL + src) * HH + h];
    __syncthreads();

    // ---- u[k] = dot(hid, Wk[kvidx[b,k]]) / sqrt(H); 2-key pipelined ----
    const float invscale = 1.0f / 27.712812921102035f;  // 1/sqrt(768)
    if (!hz) {
        const float4* hv = (const float4*)hid;
        #pragma unroll 1
        for (int j = 0; j < 16; j += 2) {
            const int k0 = wid * 16 + j;
            const int idx0 = kvidx[b * LL + k0];
            const int idx1 = kvidx[b * LL + k0 + 1];
            // row 0 is valid memory; padding handled by final select
            const float4* r0 = (const float4*)(Wk + (size_t)idx0 * HH);
            const float4* r1 = (const float4*)(Wk + (size_t)idx1 * HH);
            float s0 = 0.f, s1 = 0.f;
            #pragma unroll 6
            for (int i = lane; i < HV; i += 32) {
                float4 c = hv[i];
                float4 a0 = __ldg(r0 + i);
                float4 a1 = __ldg(r1 + i);
                s0 += a0.x * c.x + a0.y * c.y + a0.z * c.z + a0.w * c.w;
                s1 += a1.x * c.x + a1.y * c.y + a1.z * c.z + a1.w * c.w;
            }
            #pragma unroll
            for (int off = 16; off; off >>= 1) {
                s0 += __shfl_xor_sync(0xFFFFFFFFu, s0, off);
                s1 += __shfl_xor_sync(0xFFFFFFFFu, s1, off);
            }
            if (lane == 0) {
                uk[k0]     = (idx0 != 0) ? s0 * invscale : 0.f;
                uk[k0 + 1] = (idx1 != 0) ? s1 * invscale : 0.f;
            }
        }
        __syncthreads();
    }

    // ---- delta = exp(u)*pos; block sum; compact active (p, idx) ----
    float dloc = 0.f;
    if (tid < LL) {
        int pm = posm[(b * LL + q) * LL + tid];
        if (pm != 0) dloc = hz ? 1.f : expf(uk[tid]);   // exp(0)=1 when hz
    }
    float r = dloc;
    #pragma unroll
    for (int off = 16; off; off >>= 1) r += __shfl_xor_sync(0xFFFFFFFFu, r, off);
    if (lane == 0) warp_red[wid] = r;
    __syncthreads();
    if (tid == 0) {
        float t = 0.f;
        #pragma unroll
        for (int w = 0; w < 8; ++w) t += warp_red[w];
        s_dsum = t;
    }
    __syncthreads();
    const float inv = 1.f / (s_dsum + 1e-10f);

    if (tid < LL && dloc != 0.f) {
        int idx = fidx[tid];
        if (idx != 0) {
            int slot = atomicAdd(&s_nact, 1);
            cp_p[slot] = dloc * inv;
            cp_i[slot] = idx;
        }
    }
    __syncthreads();
    const int nact = s_nact;

    // ---- o[b,q,:] = sum_m p_m * Wv[idx_m,:]; unroll 16 for MLP ----
    if (tid < 192) {
        float4 acc = make_float4(0.f, 0.f, 0.f, 0.f);
        const float4* WvV = (const float4*)Wv;
        #pragma unroll 16
        for (int m = 0; m < nact; ++m) {
            float  pk = cp_p[m];
            float4 vv = __ldg(WvV + (size_t)cp_i[m] * HV + tid);
            acc.x += pk * vv.x; acc.y += pk * vv.y;
            acc.z += pk * vv.z; acc.w += pk * vv.w;
        }
        ((float4*)(g_o + (size_t)(b * LL + q) * HH))[tid] = acc;
    }
}

// Fused reduce + head. grid = 8, block = 768.
// 4 segments x 192 float4-columns; each thread: 32 independent LDG.128.
__global__ __launch_bounds__(768) void reduce_head_k(
    const float* __restrict__ pooled,  // [B,H]
    const float* __restrict__ Wd,      // [3,2H]
    const float* __restrict__ bd,      // [3]
    float*       __restrict__ out)     // [B,3]
{
    const int b   = blockIdx.x;
    const int t   = threadIdx.x;       // 0..767
    const int col = t % 192;           // float4 column
    const int seg = t / 192;           // 0..3: rows seg*32 .. seg*32+31

    __shared__ __align__(16) float4 s_s[4][192];
    __shared__ __align__(16) float4 s_c[4][192];
    __shared__ float wred[6][NLAB];

    const float4* ob = (const float4*)g_o + ((size_t)b * LL + seg * 32) * HV + col;

    float4 s = make_float4(0.f, 0.f, 0.f, 0.f);
    float4 c = make_float4(0.f, 0.f, 0.f, 0.f);
    #pragma unroll 1
    for (int r0 = 0; r0 < 32; r0 += 16) {
        float4 vv[16];
        #pragma unroll
        for (int j = 0; j < 16; ++j)
            vv[j] = ob[(size_t)(r0 + j) * HV];     // 16 independent LDG.128
        #pragma unroll
        for (int j = 0; j < 16; ++j) {
            s.x += vv[j].x; s.y += vv[j].y; s.z += vv[j].z; s.w += vv[j].w;
            c.x += (vv[j].x != 0.f) ? 1.f : 0.f;
            c.y += (vv[j].y != 0.f) ? 1.f : 0.f;
            c.z += (vv[j].z != 0.f) ? 1.f : 0.f;
            c.w += (vv[j].w != 0.f) ? 1.f : 0.f;
        }
    }
    s_s[seg][col] = s;
    s_c[seg][col] = c;
    __syncthreads();

    if (t < 192) {
        const int lane = t & 31;
        const int wid  = t >> 5;       // 0..5

        float4 ss = s_s[0][t], cc = s_c[0][t];
        #pragma unroll
        for (int g = 1; g < 4; ++g) {
            float4 ps = s_s[g][t], pc = s_c[g][t];
            ss.x += ps.x; ss.y += ps.y; ss.z += ps.z; ss.w += ps.w;
            cc.x += pc.x; cc.y += pc.y; cc.z += pc.z; cc.w += pc.w;
        }
        float4 avg = make_float4(ss.x / cc.x, ss.y / cc.y, ss.z / cc.z, ss.w / cc.w);
        float4 pv  = ((const float4*)pooled)[b * HV + t];

        #pragma unroll
        for (int n = 0; n < NLAB; ++n) {
            float4 w0 = ((const float4*)(Wd + n * 2 * HH))[t];
            float4 w1 = ((const float4*)(Wd + n * 2 * HH + HH))[t];
            float x = pv.x * w0.x + pv.y * w0.y + pv.z * w0.z + pv.w * w0.w
                    + avg.x * w1.x + avg.y * w1.y + avg.z * w1.z + avg.w * w1.w;
            #pragma unroll
            for (int off = 16; off; off >>= 1)
                x += __shfl_xor_sync(0xFFFFFFFFu, x, off);
            if (lane == 0) wred[wid][n] = x;
        }
    }
    __syncthreads();
    if (t < NLAB) {
        float tot = bd[t];
        #pragma unroll
        for (int w = 0; w < 6; ++w) tot += wred[w][t];
        out[b * NLAB + t] = tot;
    }
}

extern "C" void kernel_launch(void* const* d_in, const int* in_sizes, int n_in,
                              void* d_out, int out_size) {
    const float* seq    = (const float*)d_in[0];
    const float* pooled = (const float*)d_in[1];
    const float* Wk     = (const float*)d_in[2];
    const float* Wv     = (const float*)d_in[3];
    const float* Wd     = (const float*)d_in[4];
    const float* bd     = (const float*)d_in[5];
    const int*   valid  = (const int*)d_in[6];
    const int*   kvidx  = (const int*)d_in[7];
    const int*   feat   = (const int*)d_in[8];
    const int*   posm   = (const int*)d_in[9];
    const int*   asp    = (const int*)d_in[10];

    attn_k<<<BB * LL, 256>>>(seq, Wk, Wv, valid, kvidx, feat, posm, asp);
    reduce_head_k<<<BB, 768>>>(pooled, Wd, bd, (float*)d_out);
}